// round 15
// baseline (speedup 1.0000x reference)
#include <cuda_runtime.h>
#include <cuda_fp16.h>
#include <cstdint>
#include <math.h>

#define SX 18
#define KS 13
#define W4 28561
#define W3 2197
#define W2 169
#define X3 5832
#define X2 324
#define XB 104976
#define NB 512

#define APITCHW 12                       // u32 words per A row (24 halfs)
#define AROWS   656
#define AWORDSH (AROWS * APITCHW)        // 7872 words per A buffer
#define BWORDSH (13 * 24 * 12)           // 3744 words per B buffer
#define B0OFF   (2 * AWORDSH)            // 15744
#define TOTW    (2 * AWORDSH + 2 * BWORDSH)   // 23232 words
#define SMEM_BYTES (TOTW * 4)            // 92928 B -> 2 blocks/SM
#define NT 384

__device__ __half g_xh[(size_t)NB * XB];     // fp16 x (107.5 MB)
__device__ __half g_Bh[169 * 7488];          // fp16 Toeplitz B per (ky,kz)

__global__ void prep_x(const float* __restrict__ x) {
    size_t n4 = (size_t)NB * XB / 4;
    size_t stride = (size_t)gridDim.x * blockDim.x;
    for (size_t i = (size_t)blockIdx.x * blockDim.x + threadIdx.x; i < n4;
         i += stride) {
        float4 v = ((const float4*)x)[i];
        __half2 h0 = __floats2half2_rn(v.x, v.y);
        __half2 h1 = __floats2half2_rn(v.z, v.w);
        uint2 u; u.x = *(uint32_t*)&h0; u.y = *(uint32_t*)&h1;
        ((uint2*)g_xh)[i] = u;
    }
}

__global__ void prep_B(const float* __restrict__ cw) {
    int i = blockIdx.x;                      // 0..168
    int ky = i / 13, kz = i - 13 * (i / 13);
    uint32_t* z = (uint32_t*)(g_Bh + (size_t)i * 7488);
    for (int t = threadIdx.x; t < 3744; t += blockDim.x) z[t] = 0u;
    __syncthreads();
    for (int t = threadIdx.x; t < 507; t += blockDim.x) {
        int kx = t / 39; int r = t - kx * 39;
        int ch = r / 13; int kw = r - ch * 13;
        __half hw = __float2half_rn(cw[ch * W4 + kx * W3 + ky * W2 + kz * KS + kw]);
        __half* d = g_Bh + (size_t)i * 7488 + kx * 576 + ch * 6 * 24;
        #pragma unroll
        for (int ow = 0; ow < 6; ++ow)
            d[ow * 24 + ow + kw] = hw;       // B[n=ch*6+ow][k=ow+kw]
    }
}

__device__ __forceinline__ uint32_t smem_u32(const void* p) {
    uint32_t a; asm("{ .reg .u64 t; cvta.to.shared.u64 t, %1; cvt.u32.u64 %0, t; }"
                    : "=r"(a) : "l"(p));
    return a;
}
__device__ __forceinline__ void cp4(uint32_t dst, const void* src) {
    asm volatile("cp.async.ca.shared.global [%0], [%1], 4;"
                 :: "r"(dst), "l"(src) : "memory");
}
__device__ __forceinline__ void cp16(uint32_t dst, const void* src) {
    asm volatile("cp.async.cg.shared.global [%0], [%1], 16;"
                 :: "r"(dst), "l"(src) : "memory");
}
__device__ __forceinline__ void mma_k16(float* c, uint32_t a0, uint32_t a1,
                                        uint32_t a2, uint32_t a3,
                                        uint32_t b0, uint32_t b1) {
    asm volatile(
        "mma.sync.aligned.m16n8k16.row.col.f32.f16.f16.f32 "
        "{%0,%1,%2,%3}, {%4,%5,%6,%7}, {%8,%9}, {%0,%1,%2,%3};"
        : "+f"(c[0]), "+f"(c[1]), "+f"(c[2]), "+f"(c[3])
        : "r"(a0), "r"(a1), "r"(a2), "r"(a3), "r"(b0), "r"(b1));
}
__device__ __forceinline__ void mma_k8(float* c, uint32_t a0, uint32_t a1,
                                       uint32_t b0) {
    asm volatile(
        "mma.sync.aligned.m16n8k8.row.col.f32.f16.f16.f32 "
        "{%0,%1,%2,%3}, {%4,%5}, {%6}, {%0,%1,%2,%3};"
        : "+f"(c[0]), "+f"(c[1]), "+f"(c[2]), "+f"(c[3])
        : "r"(a0), "r"(a1), "r"(b0));
}

__global__ __launch_bounds__(NT, 2)
void conv4d_mma_h3(const float* __restrict__ cb, const float* __restrict__ lw,
                   const float* __restrict__ lb, float* __restrict__ out)
{
    extern __shared__ uint32_t smem[];
    const uint32_t sb = smem_u32(smem);

    const int b   = blockIdx.x;
    const int tid = threadIdx.x;
    const int wid = tid >> 5;
    const int lid = tid & 31;
    const int g   = lid >> 2;
    const int tig = lid & 3;

    // 12 warps = 6 m-sixths x 2 kx-halves
    const int mq  = wid >> 1;                    // 0..5, tiles 3/3/2/2/2/2
    const int kg  = wid & 1;                     // kx 0..6 / 6..12 (kx6 split)
    const int tbase  = (mq < 2) ? 3 * mq : 6 + 2 * (mq - 2);
    const int tcount = (mq < 2) ? 3 : 2;
    const int kxs = (kg == 0) ? 0 : 6;
    const int kxe = (kg == 0) ? 6 : 12;

    float c[3][3][4];
    #pragma unroll
    for (int t = 0; t < 3; ++t)
        #pragma unroll
        for (int n = 0; n < 3; ++n)
            #pragma unroll
            for (int v = 0; v < 4; ++v) c[t][n][v] = 0.f;

    // A staging offsets: (src u32-idx << 13) | dst word-idx   (16 per thread)
    uint32_t pk[16];
    #pragma unroll
    for (int k = 0; k < 16; ++k) {
        int u = tid + k * NT;
        if (u < 5832) {
            int row = u / 9;   int j   = u - row * 9;
            int ix  = row / 36; int oyz = row - ix * 36;
            int oy  = oyz / 6;  int oz  = oyz - oy * 6;
            uint32_t srcU = (uint32_t)((ix * X3 + oy * X2 + oz * SX) >> 1) + j;
            pk[k] = (srcU << 13) | (uint32_t)(row * APITCHW + j);
        } else pk[k] = 0xFFFFFFFFu;
    }

    // zero both A buffers once (k-pad words 9..11, pad rows 648..655)
    for (int w = tid; w < 2 * AWORDSH; w += NT) smem[w] = 0u;
    __syncthreads();

    const char* xh = (const char*)(g_xh + (size_t)b * XB);
    const char* bh = (const char*)g_Bh;

    // ---- prologue: stage(0) into buffers 0 ----
    {
        #pragma unroll
        for (int k = 0; k < 16; ++k) {
            uint32_t p = pk[k];
            if (p != 0xFFFFFFFFu)
                cp4(sb + (p & 8191u) * 4u, xh + (size_t)(p >> 13) * 4);
        }
        #pragma unroll
        for (int k = 0; k < 3; ++k) {
            int u = tid + k * NT;
            if (u < 936) cp16(sb + B0OFF * 4 + u * 16, bh + u * 16);
        }
        asm volatile("cp.async.commit_group;" ::: "memory");
    }

    #pragma unroll 1
    for (int i = 0; i < 169; ++i) {
        __syncthreads();               // compute(i-1) readers done everywhere

        if (i < 168) {                 // stage(i+1) into buffer (i+1)&1
            const int ni = i + 1;
            const int ky = ni / 13, kz = ni - 13 * (ni / 13);
            const uint32_t dA = (uint32_t)((ky * X2 + kz * SX) >> 1);
            const uint32_t abufB = (uint32_t)((ni & 1) * AWORDSH) * 4u;
            #pragma unroll
            for (int k = 0; k < 16; ++k) {
                uint32_t p = pk[k];
                if (p != 0xFFFFFFFFu)
                    cp4(sb + abufB + (p & 8191u) * 4u,
                        xh + (size_t)((p >> 13) + dA) * 4);
            }
            const uint32_t bbufB = (uint32_t)(B0OFF + (ni & 1) * BWORDSH) * 4u;
            const char* bsrc = bh + (size_t)ni * 14976;
            #pragma unroll
            for (int k = 0; k < 3; ++k) {
                int u = tid + k * NT;
                if (u < 936) cp16(sb + bbufB + u * 16, bsrc + u * 16);
            }
            asm volatile("cp.async.commit_group;" ::: "memory");
            asm volatile("cp.async.wait_group 1;" ::: "memory");
        } else {
            asm volatile("cp.async.wait_group 0;" ::: "memory");
        }
        __syncthreads();               // stage(i) visible

        // ---- compute(i) ----
        const uint32_t* As = smem + (i & 1) * AWORDSH;
        const uint32_t* Bw0 = smem + B0OFF + (i & 1) * BWORDSH + g * APITCHW;
        #pragma unroll 1
        for (int kx = kxs; kx <= kxe; ++kx) {
            const bool do16 = !(kx == 6 && kg == 1);
            const bool do8  = !(kx == 6 && kg == 0);
            uint32_t bf0[3], bf1[3], bf2[3];
            {
                const uint32_t* Bw = Bw0 + kx * 288;
                #pragma unroll
                for (int nt = 0; nt < 3; ++nt) {
                    const uint32_t* p = Bw + nt * 8 * APITCHW;
                    bf0[nt] = p[tig];
                    bf1[nt] = p[tig + 4];
                    bf2[nt] = p[tig + 8];
                }
            }
            #pragma unroll
            for (int t = 0; t < 3; ++t) {
                if (t < tcount) {
                    const int rg = (tbase + t) * 16 + g + 36 * kx;
                    const uint32_t* Ar = As + rg * APITCHW + tig;
                    uint32_t alo_g = Ar[0];
                    uint32_t ahi_g = Ar[4];
                    uint32_t ae_g  = Ar[8];
                    uint32_t alo_h = Ar[8 * APITCHW];
                    uint32_t ahi_h = Ar[8 * APITCHW + 4];
                    uint32_t ae_h  = Ar[8 * APITCHW + 8];
                    #pragma unroll
                    for (int nt = 0; nt < 3; ++nt) {
                        if (do16) mma_k16(c[t][nt], alo_g, alo_h, ahi_g, ahi_h,
                                          bf0[nt], bf1[nt]);
                        if (do8)  mma_k8(c[t][nt], ae_g, ae_h, bf2[nt]);
                    }
                }
            }
        }
    }

    // ---- reduce C across kg (2 phases, tile-indexed) ----
    __syncthreads();
    float* Cred = (float*)smem;
    #pragma unroll 1
    for (int ph = 0; ph < 2; ++ph) {
        if (kg == ph) {
            #pragma unroll
            for (int t = 0; t < 3; ++t)
                if (t < tcount) {
                    int tile = tbase + t;
                    #pragma unroll
                    for (int nt = 0; nt < 3; ++nt)
                        #pragma unroll
                        for (int v = 0; v < 4; ++v) {
                            int idx = ((tile * 3 + nt) * 4 + v) * 32 + lid;
                            if (ph == 0) Cred[idx] = c[t][nt][v];
                            else         Cred[idx] += c[t][nt][v];
                        }
                }
        }
        __syncthreads();
    }

    // ---- epilogue: bias + ReLU + dot(lin_w) ----
    float partial = 0.f;
    #pragma unroll 1
    for (int e = tid; e < 5376; e += NT) {
        int ln = e & 31;  int q  = e >> 5;
        int v  = q & 3;   int q2 = q >> 2;
        int nt = q2 % 3;  int tile = q2 / 3;
        int m = tile * 16 + (ln >> 2) + (v >> 1) * 8;
        int n = nt * 8 + (ln & 3) * 2 + (v & 1);
        if (m < 216 && n < 18) {
            int ox = m / 36; int oyz = m - ox * 36;
            int ch = n / 6;  int ow  = n - ch * 6;
            float h = Cred[e] + __ldg(cb + ch);
            h = fmaxf(h, 0.f);
            partial = fmaf(h, __ldg(lw + ch * 1296 + ox * 216 + oyz * 6 + ow),
                           partial);
        }
    }

    float* red = (float*)smem + 8192;
    red[tid] = partial;
    __syncthreads();
    if (tid < 128) red[tid] += red[tid + 128] + red[tid + 256];
    __syncthreads();
    if (tid < 64)  red[tid] += red[tid + 64];
    __syncthreads();
    if (tid < 32) {
        float v = red[tid] + red[tid + 32];
        #pragma unroll
        for (int off = 16; off > 0; off >>= 1)
            v += __shfl_down_sync(0xffffffffu, v, off);
        if (tid == 0) {
            float z = v + __ldg(lb);
            out[b] = 1.f / (1.f + expf(-z));
        }
    }
}

extern "C" void kernel_launch(void* const* d_in, const int* in_sizes, int n_in,
                              void* d_out, int out_size)
{
    const float* x      = (const float*)d_in[0];
    const float* conv_w = (const float*)d_in[1];
    const float* conv_b = (const float*)d_in[2];
    const float* lin_w  = (const float*)d_in[3];
    const float* lin_b  = (const float*)d_in[4];
    float* out = (float*)d_out;

    prep_x<<<4096, 256>>>(x);
    prep_B<<<169, 256>>>(conv_w);
    cudaFuncSetAttribute(conv4d_mma_h3,
                         cudaFuncAttributeMaxDynamicSharedMemorySize, SMEM_BYTES);
    conv4d_mma_h3<<<512, NT, SMEM_BYTES>>>(conv_b, lin_w, lin_b, out);
}

// round 16
// speedup vs baseline: 1.1344x; 1.1344x over previous
#include <cuda_runtime.h>
#include <cuda_fp16.h>
#include <cstdint>
#include <math.h>

#define SX 18
#define KS 13
#define W4 28561
#define W3 2197
#define W2 169
#define X3 5832
#define X2 324
#define XB 104976
#define NB 512

#define APITCHW 12                       // u32 words per A row (24 halfs)
#define AROWS   656
#define AWORDSH (AROWS * APITCHW)        // 7872 words per A buffer
#define BWORDSH (13 * 24 * 12)           // 3744 words per B buffer
#define B0OFF   (2 * AWORDSH)            // 15744
#define TOTW    (2 * AWORDSH + 2 * BWORDSH)   // 23232 words
#define SMEM_BYTES (TOTW * 4)            // 92928 B -> 2 blocks/SM
#define NT 256

__device__ __half g_xh[(size_t)NB * XB];     // fp16 x (107.5 MB)
__device__ __half g_Bh[169 * 7488];          // fp16 Toeplitz B per (ky,kz)

__global__ void prep_x(const float* __restrict__ x) {
    size_t n4 = (size_t)NB * XB / 4;
    size_t stride = (size_t)gridDim.x * blockDim.x;
    for (size_t i = (size_t)blockIdx.x * blockDim.x + threadIdx.x; i < n4;
         i += stride) {
        float4 v = ((const float4*)x)[i];
        __half2 h0 = __floats2half2_rn(v.x, v.y);
        __half2 h1 = __floats2half2_rn(v.z, v.w);
        uint2 u; u.x = *(uint32_t*)&h0; u.y = *(uint32_t*)&h1;
        ((uint2*)g_xh)[i] = u;
    }
}

__global__ void prep_B(const float* __restrict__ cw) {
    int i = blockIdx.x;                      // 0..168
    int ky = i / 13, kz = i - 13 * (i / 13);
    uint32_t* z = (uint32_t*)(g_Bh + (size_t)i * 7488);
    for (int t = threadIdx.x; t < 3744; t += blockDim.x) z[t] = 0u;
    __syncthreads();
    for (int t = threadIdx.x; t < 507; t += blockDim.x) {
        int kx = t / 39; int r = t - kx * 39;
        int ch = r / 13; int kw = r - ch * 13;
        __half hw = __float2half_rn(cw[ch * W4 + kx * W3 + ky * W2 + kz * KS + kw]);
        __half* d = g_Bh + (size_t)i * 7488 + kx * 576 + ch * 6 * 24;
        #pragma unroll
        for (int ow = 0; ow < 6; ++ow)
            d[ow * 24 + ow + kw] = hw;       // B[n=ch*6+ow][k=ow+kw]
    }
}

__device__ __forceinline__ uint32_t smem_u32(const void* p) {
    uint32_t a; asm("{ .reg .u64 t; cvta.to.shared.u64 t, %1; cvt.u32.u64 %0, t; }"
                    : "=r"(a) : "l"(p));
    return a;
}
__device__ __forceinline__ void cp4(uint32_t dst, const void* src) {
    asm volatile("cp.async.ca.shared.global [%0], [%1], 4;"
                 :: "r"(dst), "l"(src) : "memory");
}
__device__ __forceinline__ void cp16(uint32_t dst, const void* src) {
    asm volatile("cp.async.cg.shared.global [%0], [%1], 16;"
                 :: "r"(dst), "l"(src) : "memory");
}
__device__ __forceinline__ void ldsm4(uint32_t& r0, uint32_t& r1, uint32_t& r2,
                                      uint32_t& r3, uint32_t a) {
    asm volatile("ldmatrix.sync.aligned.m8n8.x4.shared.b16 {%0,%1,%2,%3}, [%4];"
                 : "=r"(r0), "=r"(r1), "=r"(r2), "=r"(r3) : "r"(a));
}
__device__ __forceinline__ void ldsm2(uint32_t& r0, uint32_t& r1, uint32_t a) {
    asm volatile("ldmatrix.sync.aligned.m8n8.x2.shared.b16 {%0,%1}, [%2];"
                 : "=r"(r0), "=r"(r1) : "r"(a));
}
__device__ __forceinline__ void ldsm1(uint32_t& r0, uint32_t a) {
    asm volatile("ldmatrix.sync.aligned.m8n8.x1.shared.b16 {%0}, [%1];"
                 : "=r"(r0) : "r"(a));
}
__device__ __forceinline__ void mma_k16(float* c, uint32_t a0, uint32_t a1,
                                        uint32_t a2, uint32_t a3,
                                        uint32_t b0, uint32_t b1) {
    asm volatile(
        "mma.sync.aligned.m16n8k16.row.col.f32.f16.f16.f32 "
        "{%0,%1,%2,%3}, {%4,%5,%6,%7}, {%8,%9}, {%0,%1,%2,%3};"
        : "+f"(c[0]), "+f"(c[1]), "+f"(c[2]), "+f"(c[3])
        : "r"(a0), "r"(a1), "r"(a2), "r"(a3), "r"(b0), "r"(b1));
}
__device__ __forceinline__ void mma_k8(float* c, uint32_t a0, uint32_t a1,
                                       uint32_t b0) {
    asm volatile(
        "mma.sync.aligned.m16n8k8.row.col.f32.f16.f16.f32 "
        "{%0,%1,%2,%3}, {%4,%5}, {%6}, {%0,%1,%2,%3};"
        : "+f"(c[0]), "+f"(c[1]), "+f"(c[2]), "+f"(c[3])
        : "r"(a0), "r"(a1), "r"(b0));
}

__global__ __launch_bounds__(NT, 2)
void conv4d_mma_ls(const float* __restrict__ cb, const float* __restrict__ lw,
                   const float* __restrict__ lb, float* __restrict__ out)
{
    extern __shared__ uint32_t smem[];
    const uint32_t sb = smem_u32(smem);

    const int b   = blockIdx.x;
    const int tid = threadIdx.x;
    const int wid = tid >> 5;
    const int lid = tid & 31;

    const int mq  = wid & 3;                     // tiles: 4/4/3/3
    const int kg  = wid >> 2;                    // kx 0..6 / 6..12 (kx6 split)
    const int tbase  = (mq < 2) ? 4 * mq : 8 + 3 * (mq - 2);
    const int tcount = (mq < 2) ? 4 : 3;
    const int kxs = (kg == 0) ? 0 : 6;
    const int kxe = (kg == 0) ? 6 : 12;

    float c[4][3][4];
    #pragma unroll
    for (int t = 0; t < 4; ++t)
        #pragma unroll
        for (int n = 0; n < 3; ++n)
            #pragma unroll
            for (int v = 0; v < 4; ++v) c[t][n][v] = 0.f;

    // ---- ldmatrix per-lane address terms (byte offsets, thread-constant) ----
    // A x4: mats (rows m0..m0+7 k0-7, rows+8 k0-7, rows k8-15, rows+8 k8-15)
    const uint32_t a_lane = (uint32_t)(lid & 15) * 48u + (uint32_t)(lid >> 4) * 16u;
    const int d_ax2 = 32 - (lid >> 4) * 16;      // x2 (k16-23): rows, word 8
    // B x4 #1: mats (nt0 k0-7, nt0 k8-15, nt1 k0-7, nt1 k8-15)
    const uint32_t b1_lane = (uint32_t)(((lid >> 4) << 3) + (lid & 7)) * 48u
                           + (uint32_t)((lid >> 3) & 1) * 16u;
    // B x4 #2: mats (nt2 k0-7, nt2 k8-15, nt0 k16-23, nt1 k16-23)
    int n2 = (lid < 16) ? 16 + (lid & 7) : ((lid < 24) ? (lid & 7) : 8 + (lid & 7));
    int w2 = (lid < 8) ? 0 : ((lid < 16) ? 16 : 32);
    const int d_b2 = n2 * 48 + w2 - (int)b1_lane;
    // B x1: mat nt2 k16-23
    const int d_b3 = (16 + (lid & 7)) * 48 + 32 - (int)b1_lane;

    // A staging offsets: (src u32-idx << 13) | dst word-idx
    uint32_t pk[23];
    #pragma unroll
    for (int k = 0; k < 23; ++k) {
        int u = tid + k * NT;
        if (u < 5832) {
            int row = u / 9;   int j   = u - row * 9;
            int ix  = row / 36; int oyz = row - ix * 36;
            int oy  = oyz / 6;  int oz  = oyz - oy * 6;
            uint32_t srcU = (uint32_t)((ix * X3 + oy * X2 + oz * SX) >> 1) + j;
            pk[k] = (srcU << 13) | (uint32_t)(row * APITCHW + j);
        } else pk[k] = 0xFFFFFFFFu;
    }

    for (int w = tid; w < 2 * AWORDSH; w += NT) smem[w] = 0u;
    __syncthreads();

    const char* xh = (const char*)(g_xh + (size_t)b * XB);
    const char* bh = (const char*)g_Bh;

    // ---- prologue: stage(0) into buffers 0 ----
    {
        #pragma unroll
        for (int k = 0; k < 23; ++k) {
            uint32_t p = pk[k];
            if (p != 0xFFFFFFFFu)
                cp4(sb + (p & 8191u) * 4u, xh + (size_t)(p >> 13) * 4);
        }
        #pragma unroll
        for (int k = 0; k < 4; ++k) {
            int u = tid + k * NT;
            if (u < 936) cp16(sb + B0OFF * 4 + u * 16, bh + u * 16);
        }
        asm volatile("cp.async.commit_group;" ::: "memory");
    }

    #pragma unroll 1
    for (int i = 0; i < 169; ++i) {
        __syncthreads();

        if (i < 168) {
            const int ni = i + 1;
            const int ky = ni / 13, kz = ni - 13 * (ni / 13);
            const uint32_t dA = (uint32_t)((ky * X2 + kz * SX) >> 1);
            const uint32_t abufB = (uint32_t)((ni & 1) * AWORDSH) * 4u;
            #pragma unroll
            for (int k = 0; k < 23; ++k) {
                uint32_t p = pk[k];
                if (p != 0xFFFFFFFFu)
                    cp4(sb + abufB + (p & 8191u) * 4u,
                        xh + (size_t)((p >> 13) + dA) * 4);
            }
            const uint32_t bbufB = (uint32_t)(B0OFF + (ni & 1) * BWORDSH) * 4u;
            const char* bsrc = bh + (size_t)ni * 14976;
            #pragma unroll
            for (int k = 0; k < 4; ++k) {
                int u = tid + k * NT;
                if (u < 936) cp16(sb + bbufB + u * 16, bsrc + u * 16);
            }
            asm volatile("cp.async.commit_group;" ::: "memory");
            asm volatile("cp.async.wait_group 1;" ::: "memory");
        } else {
            asm volatile("cp.async.wait_group 0;" ::: "memory");
        }
        __syncthreads();

        // ---- compute(i) via ldmatrix ----
        uint32_t aaddr[4];
        #pragma unroll
        for (int t = 0; t < 4; ++t)
            aaddr[t] = sb + (uint32_t)((i & 1) * AWORDSH) * 4u
                     + (uint32_t)((tbase + t) * 16) * 48u + a_lane
                     + (uint32_t)(kxs * 1728);
        uint32_t baddr = sb + (uint32_t)(B0OFF + (i & 1) * BWORDSH) * 4u
                       + b1_lane + (uint32_t)(kxs * 1152);

        #pragma unroll 1
        for (int kx = kxs; kx <= kxe; ++kx) {
            const bool do16 = !(kx == 6 && kg == 1);
            const bool do8  = !(kx == 6 && kg == 0);
            uint32_t b00, b01, b10, b11, b20, b21, be0, be1, be2;
            ldsm4(b00, b01, b10, b11, baddr);                    // nt0,nt1 k0-15
            ldsm4(b20, b21, be0, be1, baddr + (uint32_t)d_b2);   // nt2 k0-15; nt0,nt1 k16
            ldsm1(be2, baddr + (uint32_t)d_b3);                  // nt2 k16
            #pragma unroll
            for (int t = 0; t < 4; ++t) {
                if (t < tcount) {
                    uint32_t a0, a1, a2, a3, e0, e1;
                    ldsm4(a0, a1, a2, a3, aaddr[t]);
                    ldsm2(e0, e1, aaddr[t] + (uint32_t)d_ax2);
                    if (do16) {
                        mma_k16(c[t][0], a0, a1, a2, a3, b00, b01);
                        mma_k16(c[t][1], a0, a1, a2, a3, b10, b11);
                        mma_k16(c[t][2], a0, a1, a2, a3, b20, b21);
                    }
                    if (do8) {
                        mma_k8(c[t][0], e0, e1, be0);
                        mma_k8(c[t][1], e0, e1, be1);
                        mma_k8(c[t][2], e0, e1, be2);
                    }
                }
            }
            #pragma unroll
            for (int t = 0; t < 4; ++t) aaddr[t] += 1728u;
            baddr += 1152u;
        }
    }

    // ---- reduce C across kg (2 phases, tile-indexed) ----
    __syncthreads();
    float* Cred = (float*)smem;
    #pragma unroll 1
    for (int ph = 0; ph < 2; ++ph) {
        if (kg == ph) {
            #pragma unroll
            for (int t = 0; t < 4; ++t)
                if (t < tcount) {
                    int tile = tbase + t;
                    #pragma unroll
                    for (int nt = 0; nt < 3; ++nt)
                        #pragma unroll
                        for (int v = 0; v < 4; ++v) {
                            int idx = ((tile * 3 + nt) * 4 + v) * 32 + lid;
                            if (ph == 0) Cred[idx] = c[t][nt][v];
                            else         Cred[idx] += c[t][nt][v];
                        }
                }
        }
        __syncthreads();
    }

    // ---- epilogue: bias + ReLU + dot(lin_w) ----
    float partial = 0.f;
    #pragma unroll 1
    for (int e = tid; e < 5376; e += NT) {
        int ln = e & 31;  int q  = e >> 5;
        int v  = q & 3;   int q2 = q >> 2;
        int nt = q2 % 3;  int tile = q2 / 3;
        int m = tile * 16 + (ln >> 2) + (v >> 1) * 8;
        int n = nt * 8 + (ln & 3) * 2 + (v & 1);
        if (m < 216 && n < 18) {
            int ox = m / 36; int oyz = m - ox * 36;
            int ch = n / 6;  int ow  = n - ch * 6;
            float h = Cred[e] + __ldg(cb + ch);
            h = fmaxf(h, 0.f);
            partial = fmaf(h, __ldg(lw + ch * 1296 + ox * 216 + oyz * 6 + ow),
                           partial);
        }
    }

    float* red = (float*)smem + 8192;
    red[tid] = partial;
    __syncthreads();
    if (tid < 128) red[tid] += red[tid + 128];
    __syncthreads();
    if (tid < 64)  red[tid] += red[tid + 64];
    __syncthreads();
    if (tid < 32) {
        float v = red[tid] + red[tid + 32];
        #pragma unroll
        for (int off = 16; off > 0; off >>= 1)
            v += __shfl_down_sync(0xffffffffu, v, off);
        if (tid == 0) {
            float z = v + __ldg(lb);
            out[b] = 1.f / (1.f + expf(-z));
        }
    }
}

extern "C" void kernel_launch(void* const* d_in, const int* in_sizes, int n_in,
                              void* d_out, int out_size)
{
    const float* x      = (const float*)d_in[0];
    const float* conv_w = (const float*)d_in[1];
    const float* conv_b = (const float*)d_in[2];
    const float* lin_w  = (const float*)d_in[3];
    const float* lin_b  = (const float*)d_in[4];
    float* out = (float*)d_out;

    prep_x<<<4096, 256>>>(x);
    prep_B<<<169, 256>>>(conv_w);
    cudaFuncSetAttribute(conv4d_mma_ls,
                         cudaFuncAttributeMaxDynamicSharedMemorySize, SMEM_BYTES);
    conv4d_mma_ls<<<512, NT, SMEM_BYTES>>>(conv_b, lin_w, lin_b, out);
}